// round 11
// baseline (speedup 1.0000x reference)
#include <cuda_runtime.h>

// B3-spline à-trous undecimated wavelet transform, J=3, fused single kernel.
// Input  x: (B, 1024, 1024) fp32.  Output: (B, 4, 1024, 1024) = [w1, w2, w3, c3].
//
// Tile 64x64/CTA, cascaded halo 14 (2+4+8). Symmetric taps => conv(reflect) ==
// reflect(conv): one reflect-padded c0 load matches per-level reflect padding.
//
// R8: convX-FIRST ordering. Each level is
//   tpassX: c_{j-1}[x][y] -> t[y][x]   (conv along x, STS.128 stores)
//   tpassY: t[y][x] -> c_j[x][y]       (conv along y, scalar STS)
// In tpassY, registers i hold y and lanes hold x, so w_j = c_{j-1} - c_j (and
// c_3) are stored straight from registers as coalesced gmem rows: the three
// standalone writeout phases and ALL c3 smem traffic are gone (-18% smem
// wavefronts, 1 fewer barrier). Mixed strides keep everything conflict-free:
//   A, C ([x][y] c-planes): stride 93 (odd)  - transposed scalar STS ok,
//                                              lane-strided prev reads ok
//   B    ([y][x] t-plane) : stride 100       - 8-lane STS.128 phases hit
//                                              disjoint 4-bank groups
// Buffers: A: c0 -> c2;  B: t1 -> t2 -> t3;  C: c1.

#define IMG_H 1024
#define IMG_W 1024
#define TILE 64
#define SA 93                    // odd stride: [x][y] c-planes
#define SB 100                   // [y][x] t-plane, STS.128-friendly
#define BUFA (92 * SA)
#define BUFB (92 * SB)
#define SMEM_BYTES ((2 * BUFA + BUFB) * 4)
#define NW 24                    // warps per CTA (768 threads)

#define W0 0.0625f
#define W1 0.25f
#define W2 0.375f

__device__ __forceinline__ int refl(int i) {
    if (i < 0) return -i;
    if (i >= IMG_H) return 2 * IMG_H - 2 - i;
    return i;
}

// convX: src = c[x][y] (stride SA), conv along x, dst = t[y][x] (stride SB),
// transposed STS.128 stores. RR: output x extent, RC: carried y extent.
template <int D, int RR, int RC>
__device__ __forceinline__ void tpassX(const float* __restrict__ src,
                                       float* __restrict__ dst,
                                       int warp, int lane) {
    constexpr int GC = (RC + 31) / 32;
    constexpr int GR = RR / 8;
    constexpr int L = 8 + 4 * D;
    for (int g = warp; g < GC * GR; g += NW) {
        int c  = (g % GC) * 32 + lane;    // y index
        int r0 = (g / GC) * 8;            // x base
        if (c >= RC) continue;
        float v[L];
#pragma unroll
        for (int i = 0; i < L; i++) v[i] = src[(r0 + i) * SA + c];
        float o[8];
#pragma unroll
        for (int i = 0; i < 8; i++)
            o[i] = W0 * (v[i] + v[i + 4 * D]) + W1 * (v[i + D] + v[i + 3 * D]) +
                   W2 * v[i + 2 * D];
        float4* dp = (float4*)(dst + c * SB + r0);   // 100c+r0 % 4 == 0
        dp[0] = make_float4(o[0], o[1], o[2], o[3]);
        dp[1] = make_float4(o[4], o[5], o[6], o[7]);
    }
}

// convY: src = t[y][x] (stride SB), conv along y, optional dst = c_j[x][y]
// (stride SA, scalar transposed STS). Registers i = y, lanes = x, so the fused
// w_j = c_{j-1} - c_j (and c_J) gmem stores are coalesced rows.
// HALO: tile offset in c_j coords. PO: index offset into prev (c_{j-1}[x][y]).
template <int D, int RR, int RC, int HALO, int PO, bool STORE, bool LAST>
__device__ __forceinline__ void tpassY(const float* __restrict__ src,
                                       float* __restrict__ dst,
                                       const float* __restrict__ prev,
                                       float* __restrict__ gw,
                                       float* __restrict__ gc,
                                       int warp, int lane) {
    constexpr int GC = (RC + 31) / 32;
    constexpr int GR = RR / 8;
    constexpr int L = 8 + 4 * D;
    for (int g = warp; g < GC * GR; g += NW) {
        int c  = (g % GC) * 32 + lane;    // x index
        int r0 = (g / GC) * 8;            // y base
        if (c >= RC) continue;
        float v[L];
#pragma unroll
        for (int i = 0; i < L; i++) v[i] = src[(r0 + i) * SB + c];
        const bool xok = (c >= HALO) && (c < HALO + TILE);
        const float* pp = prev + (c + PO) * SA + (r0 + PO);
        float* gwp = gw + (size_t)(r0 - HALO) * IMG_W + (c - HALO);
        float* gcp = LAST ? gc + (size_t)(r0 - HALO) * IMG_W + (c - HALO) : nullptr;
#pragma unroll
        for (int i = 0; i < 8; i++) {
            float o = W0 * (v[i] + v[i + 4 * D]) + W1 * (v[i + D] + v[i + 3 * D]) +
                      W2 * v[i + 2 * D];
            if (STORE) dst[c * SA + r0 + i] = o;
            int yt = r0 + i - HALO;
            if (xok && yt >= 0 && yt < TILE) {
                gwp[(size_t)i * IMG_W] = pp[i] - o;
                if (LAST) gcp[(size_t)i * IMG_W] = o;
            }
        }
    }
}

__global__ __launch_bounds__(32 * NW, 2)
void uwt_kernel(const float* __restrict__ x, float* __restrict__ out) {
    extern __shared__ float sm[];
    float* A  = sm;                      // c0[x][y] -> c2[x][y]   (stride SA)
    float* Bb = sm + BUFA;               // t1 -> t2 -> t3 [y][x]  (stride SB)
    float* Cc = sm + BUFA + BUFB;        // c1[x][y]               (stride SA)

    const int tid  = threadIdx.x;
    const int lane = tid & 31;
    const int warp = tid >> 5;
    const int tx0  = blockIdx.x * TILE;
    const int ty0  = blockIdx.y * TILE;
    const int b    = blockIdx.z;

    const float* xb = x + (size_t)b * IMG_H * IMG_W;

    // Load c0 region 92x92 (origin ty0-14, tx0-14, reflect) TRANSPOSED into
    // A[x][y]: gmem reads coalesced along x; STS lanes along x, odd stride.
    for (int yl = warp; yl < 92; yl += NW) {
        const float* row = xb + (size_t)refl(ty0 - 14 + yl) * IMG_W;
#pragma unroll
        for (int cg = 0; cg < 3; cg++) {
            int xl = cg * 32 + lane;
            if (xl < 92) A[xl * SA + yl] = row[refl(tx0 - 14 + xl)];
        }
    }
    __syncthreads();

    float* base = out + (size_t)b * 4 * IMG_H * IMG_W;
    float* w1p = base + 0 * (size_t)IMG_H * IMG_W + (size_t)ty0 * IMG_W + tx0;
    float* w2p = base + 1 * (size_t)IMG_H * IMG_W + (size_t)ty0 * IMG_W + tx0;
    float* w3p = base + 2 * (size_t)IMG_H * IMG_W + (size_t)ty0 * IMG_W + tx0;
    float* c3p = base + 3 * (size_t)IMG_H * IMG_W + (size_t)ty0 * IMG_W + tx0;

    // Level 1 (d=1): t1 = convX(c0): A -> B   (x: 92->88, y: 92)
    tpassX<1, 88, 92>(A, Bb, warp, lane);
    __syncthreads();
    // c1 = convY(t1): B -> C (88x88, origin -12); fused w1 = c0 - c1.
    tpassY<1, 88, 88, 12, 2, true, false>(Bb, Cc, A, w1p, nullptr, warp, lane);
    __syncthreads();

    // Level 2 (d=2): t2 = convX(c1): C -> B   (x: 88->80, y: 88)
    tpassX<2, 80, 88>(Cc, Bb, warp, lane);
    __syncthreads();
    // c2 = convY(t2): B -> A (80x80, origin -8); fused w2 = c1 - c2.
    tpassY<2, 80, 80, 8, 4, true, false>(Bb, A, Cc, w2p, nullptr, warp, lane);
    __syncthreads();

    // Level 3 (d=4): t3 = convX(c2): A -> B   (x: 80->64, y: 80)
    tpassX<4, 64, 80>(A, Bb, warp, lane);
    __syncthreads();
    // c3 = convY(t3), registers only; fused w3 = c2 - c3 and c3 (no smem).
    tpassY<4, 64, 64, 0, 8, false, true>(Bb, nullptr, A, w3p, c3p, warp, lane);
}

extern "C" void kernel_launch(void* const* d_in, const int* in_sizes, int n_in,
                              void* d_out, int out_size) {
    const float* x = (const float*)d_in[0];
    float* out = (float*)d_out;
    int batch = in_sizes[0] / (IMG_H * IMG_W);

    cudaFuncSetAttribute(uwt_kernel, cudaFuncAttributeMaxDynamicSharedMemorySize,
                         SMEM_BYTES);

    dim3 grid(IMG_W / TILE, IMG_H / TILE, batch);
    dim3 block(32 * NW);
    uwt_kernel<<<grid, block, SMEM_BYTES>>>(x, out);
}

// round 13
// speedup vs baseline: 1.0132x; 1.0132x over previous
#include <cuda_runtime.h>

// B3-spline à-trous undecimated wavelet transform, J=3, fused single kernel.
// Input  x: (B, 1024, 1024) fp32.  Output: (B, 4, 1024, 1024) = [w1, w2, w3, c3].
//
// Tile 64x64/CTA, cascaded halo 14 (2+4+8). Symmetric taps => conv(reflect) ==
// reflect(conv): one reflect-padded c0 load matches per-level reflect padding.
//
// R9 hybrid: convX-first ordering (R8) but output fusion ONLY where it is
// predicate-free:
//   P1 tpassX c0->t1          P2 tpassY t1->c1
//   P3 tpassX c1->t2 + W1     P4 tpassY t2->c2
//   P5 tpassX c2->t3 + W2     P6 tpassY t3 -> registers -> gmem w3,c3
// P6 has RC=64=TILE and HALO=0: no bounds checks, no STS (c3 skips smem),
// coalesced STG straight from conv registers. W1/W2 are R7-style balanced
// writeout loops riding inside P3/P5 (they only read c-planes those phases
// don't write). 6 barriers (was 7), c3 smem round-trip eliminated.
//
// Strides: c-planes [x][y] use SA=93 (odd => transposed scalar STS and
// lane-strided reads conflict-free); t-planes [y][x] use SB=100 (8-lane
// STS.128 phases hit disjoint 4-bank groups). Per-buffer origins
// (c0:-14, c1:-12, c2:-8, c3:0) make all conv source offsets ZERO.
// Buffers: A: c0 -> c2;  B: t1 -> t2 -> t3;  C: c1.

#define IMG_H 1024
#define IMG_W 1024
#define TILE 64
#define SA 93
#define SB 100
#define BUFA (92 * SA)
#define BUFB (92 * SB)
#define SMEM_BYTES ((2 * BUFA + BUFB) * 4)
#define NW 24                    // warps per CTA (768 threads)

#define W0 0.0625f
#define W1f 0.25f
#define W2f 0.375f

__device__ __forceinline__ int refl(int i) {
    if (i < 0) return -i;
    if (i >= IMG_H) return 2 * IMG_H - 2 - i;
    return i;
}

// convX: src = c[x][y] (SA), conv along x (row dim), dst = t[y][x] (SB),
// STS.128 transposed stores. RR: out x extent, RC: carried y extent.
template <int D, int RR, int RC>
__device__ __forceinline__ void tpassX(const float* __restrict__ src,
                                       float* __restrict__ dst,
                                       int warp, int lane) {
    constexpr int GC = (RC + 31) / 32;
    constexpr int GR = RR / 8;
    constexpr int L = 8 + 4 * D;
    for (int g = warp; g < GC * GR; g += NW) {
        int c  = (g % GC) * 32 + lane;    // y
        int r0 = (g / GC) * 8;            // x base
        if (c >= RC) continue;
        float v[L];
#pragma unroll
        for (int i = 0; i < L; i++) v[i] = src[(r0 + i) * SA + c];
        float o[8];
#pragma unroll
        for (int i = 0; i < 8; i++)
            o[i] = W0 * (v[i] + v[i + 4 * D]) + W1f * (v[i + D] + v[i + 3 * D]) +
                   W2f * v[i + 2 * D];
        float4* dp = (float4*)(dst + c * SB + r0);   // 16B-aligned
        dp[0] = make_float4(o[0], o[1], o[2], o[3]);
        dp[1] = make_float4(o[4], o[5], o[6], o[7]);
    }
}

// convY (mid levels): src = t[y][x] (SB), conv along y, dst = c_j[x][y] (SA).
template <int D, int RR, int RC>
__device__ __forceinline__ void tpassY(const float* __restrict__ src,
                                       float* __restrict__ dst,
                                       int warp, int lane) {
    constexpr int GC = (RC + 31) / 32;
    constexpr int GR = RR / 8;
    constexpr int L = 8 + 4 * D;
    for (int g = warp; g < GC * GR; g += NW) {
        int c  = (g % GC) * 32 + lane;    // x
        int r0 = (g / GC) * 8;            // y base
        if (c >= RC) continue;
        float v[L];
#pragma unroll
        for (int i = 0; i < L; i++) v[i] = src[(r0 + i) * SB + c];
#pragma unroll
        for (int i = 0; i < 8; i++)
            dst[c * SA + r0 + i] =
                W0 * (v[i] + v[i + 4 * D]) + W1f * (v[i + D] + v[i + 3 * D]) +
                W2f * v[i + 2 * D];
    }
}

// convY final (d=4, 64x64): predicate-free; c3 never touches smem.
// lanes = x => coalesced STG of w3 = c2 - c3 and c3 from registers.
__device__ __forceinline__ void tpassY_last(const float* __restrict__ src,  // t3 (SB)
                                            const float* __restrict__ prev, // c2 (SA)
                                            float* __restrict__ gw,
                                            float* __restrict__ gc,
                                            int warp, int lane) {
    constexpr int GC = 2, GR = 8, L = 24;
    for (int g = warp; g < GC * GR; g += NW) {
        int c  = (g % GC) * 32 + lane;    // x: 0..63
        int r0 = (g / GC) * 8;            // y base
        float v[L];
#pragma unroll
        for (int i = 0; i < L; i++) v[i] = src[(r0 + i) * SB + c];
        const float* pp = prev + (c + 8) * SA + (r0 + 8);
        float* gwp = gw + (size_t)r0 * IMG_W + c;
        float* gcp = gc + (size_t)r0 * IMG_W + c;
#pragma unroll
        for (int i = 0; i < 8; i++) {
            float o = W0 * (v[i] + v[i + 16]) + W1f * (v[i + 4] + v[i + 12]) +
                      W2f * v[i + 8];
            gwp[(size_t)i * IMG_W] = pp[i] - o;
            gcp[(size_t)i * IMG_W] = o;
        }
    }
}

// Balanced writeout on [x][y] planes: w = prev - cur, coalesced gmem rows.
template <int HP, int HC>
__device__ __forceinline__ void writeout(const float* __restrict__ prev,
                                         const float* __restrict__ cur,
                                         float* __restrict__ gw, int tid) {
    int yt = tid >> 6;           // 0..11
    int xt = tid & 63;
    const float* pp = prev + (HP + xt) * SA + (HP + yt);
    const float* cp = cur + (HC + xt) * SA + (HC + yt);
    float* gwp = gw + (size_t)yt * IMG_W + xt;
#pragma unroll
    for (int i = 0; i < 6; i++) {
        int y = yt + i * 12;
        if (y < TILE) gwp[(size_t)i * 12 * IMG_W] = pp[i * 12] - cp[i * 12];
    }
}

__global__ __launch_bounds__(32 * NW, 2)
void uwt_kernel(const float* __restrict__ x, float* __restrict__ out) {
    extern __shared__ float sm[];
    float* A  = sm;                      // c0[x][y] -> c2[x][y]  (SA)
    float* Bb = sm + BUFA;               // t1 -> t2 -> t3 [y][x] (SB)
    float* Cc = sm + BUFA + BUFB;        // c1[x][y]              (SA)

    const int tid  = threadIdx.x;
    const int lane = tid & 31;
    const int warp = tid >> 5;
    const int tx0  = blockIdx.x * TILE;
    const int ty0  = blockIdx.y * TILE;
    const int b    = blockIdx.z;

    const float* xb = x + (size_t)b * IMG_H * IMG_W;

    // Load c0 region 92x92 (origin -14, reflect) transposed into A[x][y].
    for (int yl = warp; yl < 92; yl += NW) {
        const float* row = xb + (size_t)refl(ty0 - 14 + yl) * IMG_W;
#pragma unroll
        for (int cg = 0; cg < 3; cg++) {
            int xl = cg * 32 + lane;
            if (xl < 92) A[xl * SA + yl] = row[refl(tx0 - 14 + xl)];
        }
    }
    __syncthreads();

    float* base = out + (size_t)b * 4 * IMG_H * IMG_W;
    float* w1p = base + 0 * (size_t)IMG_H * IMG_W + (size_t)ty0 * IMG_W + tx0;
    float* w2p = base + 1 * (size_t)IMG_H * IMG_W + (size_t)ty0 * IMG_W + tx0;
    float* w3p = base + 2 * (size_t)IMG_H * IMG_W + (size_t)ty0 * IMG_W + tx0;
    float* c3p = base + 3 * (size_t)IMG_H * IMG_W + (size_t)ty0 * IMG_W + tx0;

    // P1: t1 = convX(c0): A -> B   (x 92->88, y 92)
    tpassX<1, 88, 92>(A, Bb, warp, lane);
    __syncthreads();
    // P2: c1 = convY(t1): B -> C   (88x88, origin -12)
    tpassY<1, 88, 88>(Bb, Cc, warp, lane);
    __syncthreads();
    // P3: t2 = convX(c1): C -> B  (+ w1 = c0 - c1; reads A,C only)
    tpassX<2, 80, 88>(Cc, Bb, warp, lane);
    writeout<14, 12>(A, Cc, w1p, tid);
    __syncthreads();
    // P4: c2 = convY(t2): B -> A   (80x80, origin -8; c0 dead)
    tpassY<2, 80, 80>(Bb, A, warp, lane);
    __syncthreads();
    // P5: t3 = convX(c2): A -> B  (+ w2 = c1 - c2; reads C,A only)
    tpassX<4, 64, 80>(A, Bb, warp, lane);
    writeout<12, 8>(Cc, A, w2p, tid);
    __syncthreads();
    // P6: c3 = convY(t3) in registers; w3 = c2 - c3 and c3 straight to gmem.
    tpassY_last(Bb, A, w3p, c3p, warp, lane);
}

extern "C" void kernel_launch(void* const* d_in, const int* in_sizes, int n_in,
                              void* d_out, int out_size) {
    const float* x = (const float*)d_in[0];
    float* out = (float*)d_out;
    int batch = in_sizes[0] / (IMG_H * IMG_W);

    cudaFuncSetAttribute(uwt_kernel, cudaFuncAttributeMaxDynamicSharedMemorySize,
                         SMEM_BYTES);

    dim3 grid(IMG_W / TILE, IMG_H / TILE, batch);
    dim3 block(32 * NW);
    uwt_kernel<<<grid, block, SMEM_BYTES>>>(x, out);
}